// round 4
// baseline (speedup 1.0000x reference)
#include <cuda_runtime.h>
#include <cuda_fp16.h>
#include <cstdint>

// Problem: B=256, T=512, H=1024, O=1 LSTM decoder.
// Persistent-kernel design: 128 CTAs (1/SM), global barrier per timestep.
// gates = x_t*w_in + h @ W_hh^T + bias  via HMMA (mma.sync m16n8k16, fp16 in / fp32 acc)
// W_hh slice resident in SMEM, c-state in registers, h ping-pong fp16 in global.

static constexpr int Tn = 512;
static constexpr int Bn = 256;
static constexpr int Hn = 1024;
static constexpr int GRID  = 128;
static constexpr int NTHR  = 256;
static constexpr int MTILE = 128;   // batch rows per CTA
static constexpr int HCOL  = 16;    // h columns per CTA
static constexpr int NGCOL = 64;    // gate columns per CTA (4*HCOL)
static constexpr int A_STR = 136;   // halfs, padded (conflict-free ldmatrix)
static constexpr int B_STR = 1032;  // halfs, padded

static constexpr int OFF_X    = 0;                      // 128 f32
static constexpr int OFF_BIAS = 512;                    // 64 f32
static constexpr int OFF_WIN  = 768;                    // 64 f32
static constexpr int OFF_A    = 1024;                   // 2 A buffers
static constexpr int ABUF_SZ  = MTILE * A_STR * 2;      // 34816 B
static constexpr int OFF_W    = OFF_A + 2 * ABUF_SZ;    // 70656
static constexpr int SMEM_SZ  = OFF_W + NGCOL * B_STR * 2;  // 202752 B

// device-global scratch (no allocation allowed)
__device__ __align__(16) __half g_hbuf[2][Bn * Hn];
__device__ unsigned g_bar;

// ---------------- helpers ----------------
__device__ __forceinline__ uint32_t smem_u32(const void* p) {
    uint32_t a;
    asm("{ .reg .u64 t; cvta.to.shared.u64 t, %1; cvt.u32.u64 %0, t; }" : "=r"(a) : "l"(p));
    return a;
}
__device__ __forceinline__ unsigned ld_acquire_gpu(const unsigned* p) {
    unsigned v;
    asm volatile("ld.acquire.gpu.global.u32 %0, [%1];" : "=r"(v) : "l"(p) : "memory");
    return v;
}
#define LDSM_X4(r0, r1, r2, r3, addr)                                         \
    asm volatile("ldmatrix.sync.aligned.m8n8.x4.shared.b16 {%0,%1,%2,%3},[%4];" \
                 : "=r"(r0), "=r"(r1), "=r"(r2), "=r"(r3) : "r"(addr))

#define MMA16816(d, a, b0v, b1v)                                              \
    asm volatile("mma.sync.aligned.m16n8k16.row.col.f32.f16.f16.f32 "         \
                 "{%0,%1,%2,%3},{%4,%5,%6,%7},{%8,%9},{%0,%1,%2,%3};"         \
                 : "+f"((d)[0]), "+f"((d)[1]), "+f"((d)[2]), "+f"((d)[3])     \
                 : "r"((a)[0]), "r"((a)[1]), "r"((a)[2]), "r"((a)[3]),        \
                   "r"(b0v), "r"(b1v))

__device__ __forceinline__ float sigmoidf_(float x) {
    return __fdividef(1.0f, 1.0f + __expf(-x));
}
__device__ __forceinline__ float tanhf_(float x) {
    x = fminf(fmaxf(x, -15.0f), 15.0f);
    float e = __expf(-2.0f * x);
    return __fdividef(1.0f - e, 1.0f + e);
}

// ---------------- prologue: reset barrier, h0 -> fp16 ping buffer ----------------
__global__ void lstm_prologue(const float* __restrict__ h0) {
    if (blockIdx.x == 0 && threadIdx.x == 0) g_bar = 0u;
    int i = blockIdx.x * 256 + threadIdx.x;   // grid 1024 x 256 = 262144
    g_hbuf[0][i] = __float2half(h0[i]);
}

// ---------------- persistent LSTM ----------------
__global__ void __launch_bounds__(NTHR, 1)
lstm_persist(const float* __restrict__ y_hist, const float* __restrict__ W_ih,
             const float* __restrict__ W_hh,   const float* __restrict__ b_ih,
             const float* __restrict__ b_hh,   const float* __restrict__ c0) {
    extern __shared__ char smem[];
    float* x_s    = (float*)(smem + OFF_X);
    float* bias_s = (float*)(smem + OFF_BIAS);
    float* win_s  = (float*)(smem + OFF_WIN);
    const uint32_t su = smem_u32(smem);

    const int tid = threadIdx.x, lid = tid & 31, wid = tid >> 5;
    const int wm = wid >> 1, wn = wid & 1;          // 4 M-warps x 2 N-warps
    const int bx = blockIdx.x, mi = bx & 1, ci = bx >> 1;
    const int m0 = mi * MTILE, j0 = ci * HCOL;

    // per-CTA constants: bias = b_ih + b_hh, w_in  (col c -> gate=c&3, jj=c>>2)
    if (tid < NGCOL) {
        int gate = tid & 3, jj = tid >> 2;
        int n = gate * Hn + j0 + jj;
        bias_s[tid] = b_ih[n] + b_hh[n];
        win_s[tid]  = W_ih[n];
    }
    // resident W slice: row r = jj*4+gate holds W_hh[gate*1024 + j0+jj][0..1023] fp16
    for (int e = tid; e < NGCOL * Hn / 8; e += NTHR) {
        int r = e >> 7, kg = (e & 127) << 3;
        int gate = r & 3, jj = r >> 2;
        const float* src = W_hh + (size_t)(gate * Hn + j0 + jj) * Hn + kg;
        float4 f0 = *(const float4*)src;
        float4 f1 = *(const float4*)(src + 4);
        __half hv[8];
        hv[0] = __float2half(f0.x); hv[1] = __float2half(f0.y);
        hv[2] = __float2half(f0.z); hv[3] = __float2half(f0.w);
        hv[4] = __float2half(f1.x); hv[5] = __float2half(f1.y);
        hv[6] = __float2half(f1.z); hv[7] = __float2half(f1.w);
        *(uint4*)(smem + OFF_W + (size_t)(r * B_STR + kg) * 2) = *(const uint4*)hv;
    }

    // ldmatrix base offsets (bytes from smem base)
    const int aRow  = lid & 15;
    const int aColB = (lid >> 4) * 16;  // +8 halfs for lanes 16..31
    int aOff[2];
#pragma unroll
    for (int mt = 0; mt < 2; ++mt)
        aOff[mt] = OFF_A + ((wm * 32 + mt * 16 + aRow) * A_STR) * 2 + aColB;
    const int bRow  = (lid & 7) + ((lid >> 4) << 3);
    const int bColB = (lid & 8) ? 16 : 0;
    int bOff[2];
#pragma unroll
    for (int np = 0; np < 2; ++np)
        bOff[np] = OFF_W + ((wn * 32 + np * 16 + bRow) * B_STR) * 2 + bColB;

    // cell-state registers: cell (row, jj) per (mt, nt)
    const int rowL   = (lid >> 2) + 8 * (lid & 1);         // 0..15
    const int jjL    = wn * 8 + ((lid & 3) >> 1);          // local jj base (+nt*2)
    const int baseRow = m0 + wm * 32 + rowL;
    float cst[8];
#pragma unroll
    for (int mt = 0; mt < 2; ++mt)
#pragma unroll
        for (int nt = 0; nt < 4; ++nt)
            cst[mt * 4 + nt] = c0[(size_t)(baseRow + mt * 16) * Hn + j0 + jjL + nt * 2];

    const int rA  = tid >> 4;          // A-copy row base (0..15), +16u
    const int cu8 = (tid & 15) << 3;   // A-copy col (halfs)

    unsigned bar_target = GRID;

    for (int t = 0; t < Tn; ++t) {
        const __half* hsrc = g_hbuf[t & 1] + (size_t)m0 * Hn;
        __half* hdst = g_hbuf[(t + 1) & 1];

        if (tid < MTILE) x_s[tid] = y_hist[(size_t)(m0 + tid) * Tn + t];

        // chunk 0 load (direct)
#pragma unroll
        for (int u = 0; u < 8; ++u) {
            int r = rA + u * 16;
            uint4 v = __ldcg((const uint4*)(hsrc + (size_t)r * Hn + cu8));
            *(uint4*)(smem + OFF_A + (size_t)(r * A_STR + cu8) * 2) = v;
        }
        __syncthreads();

        float d[2][4][4] = {};
        int p = 0;
#pragma unroll 1
        for (int kc = 0; kc < 8; ++kc) {
            uint4 v[8];
            if (kc < 7) {
#pragma unroll
                for (int u = 0; u < 8; ++u) {
                    int r = rA + u * 16;
                    v[u] = __ldcg((const uint4*)(hsrc + (size_t)r * Hn + cu8 + (kc + 1) * 128));
                }
            }
#pragma unroll
            for (int ks = 0; ks < 8; ++ks) {
                uint32_t a[2][4], bb[2][4];
#pragma unroll
                for (int mt = 0; mt < 2; ++mt) {
                    uint32_t ad = su + aOff[mt] + p * ABUF_SZ + ks * 32;
                    LDSM_X4(a[mt][0], a[mt][1], a[mt][2], a[mt][3], ad);
                }
#pragma unroll
                for (int np = 0; np < 2; ++np) {
                    uint32_t bd = su + bOff[np] + kc * 256 + ks * 32;
                    LDSM_X4(bb[np][0], bb[np][1], bb[np][2], bb[np][3], bd);
                }
#pragma unroll
                for (int mt = 0; mt < 2; ++mt)
#pragma unroll
                    for (int nt = 0; nt < 4; ++nt)
                        MMA16816(d[mt][nt], a[mt],
                                 bb[nt >> 1][(nt & 1) * 2], bb[nt >> 1][(nt & 1) * 2 + 1]);
            }
            if (kc < 7) {
#pragma unroll
                for (int u = 0; u < 8; ++u) {
                    int r = rA + u * 16;
                    *(uint4*)(smem + OFF_A + (p ^ 1) * ABUF_SZ + (size_t)(r * A_STR + cu8) * 2) = v[u];
                }
                __syncthreads();
                p ^= 1;
            }
        }

        // epilogue: add rank-1 x term + bias, exchange gate pairs, LSTM cell
#pragma unroll
        for (int mt = 0; mt < 2; ++mt) {
            float x0 = x_s[wm * 32 + mt * 16 + (lid >> 2)];
            float x1 = x_s[wm * 32 + mt * 16 + (lid >> 2) + 8];
#pragma unroll
            for (int nt = 0; nt < 4; ++nt) {
                int col0 = wn * 32 + nt * 8 + (lid & 3) * 2;
                float w0 = win_s[col0], w1 = win_s[col0 + 1];
                float z0 = bias_s[col0], z1 = bias_s[col0 + 1];
                float g0 = d[mt][nt][0] + x0 * w0 + z0;   // (row r,   col0)
                float g1 = d[mt][nt][1] + x0 * w1 + z1;   // (row r,   col0+1)
                float g2 = d[mt][nt][2] + x1 * w0 + z0;   // (row r+8, col0)
                float g3 = d[mt][nt][3] + x1 * w1 + z1;   // (row r+8, col0+1)
                float p0 = __shfl_xor_sync(~0u, g0, 1);
                float p1 = __shfl_xor_sync(~0u, g1, 1);
                float p2 = __shfl_xor_sync(~0u, g2, 1);
                float p3 = __shfl_xor_sync(~0u, g3, 1);
                float gi, gf, gg, go;
                if ((lid & 1) == 0) { gi = g0; gf = g1; gg = p0; go = p1; }   // row r
                else                { gi = p2; gf = p3; gg = g2; go = g3; }   // row r+8
                float c_old = cst[mt * 4 + nt];
                float cn = sigmoidf_(gf) * c_old + sigmoidf_(gi) * tanhf_(gg);
                cst[mt * 4 + nt] = cn;
                float hn = sigmoidf_(go) * tanhf_(cn);
                hdst[(size_t)(baseRow + mt * 16) * Hn + j0 + jjL + nt * 2] = __float2half(hn);
            }
        }

        if (t != Tn - 1) {
            __threadfence();
            __syncthreads();
            if (tid == 0) {
                atomicAdd(&g_bar, 1u);
                while (ld_acquire_gpu(&g_bar) < bar_target) { }
            }
            __syncthreads();
            bar_target += GRID;
        }
    }
}

// ---------------- final FC: out[b] = h_T[b] . W_fc + b_fc ----------------
__global__ void lstm_fc(const float* __restrict__ W_fc, const float* __restrict__ b_fc,
                        float* __restrict__ out) {
    int b = blockIdx.x, l = threadIdx.x;
    const __half* h = g_hbuf[0] + (size_t)b * Hn;   // h_512 lives in buffer 0 (T even)
    float acc = 0.0f;
#pragma unroll 8
    for (int k = l; k < Hn; k += 32)
        acc += __half2float(h[k]) * W_fc[k];
#pragma unroll
    for (int o = 16; o; o >>= 1) acc += __shfl_xor_sync(~0u, acc, o);
    if (l == 0) out[b] = acc + b_fc[0];
}

extern "C" void kernel_launch(void* const* d_in, const int* in_sizes, int n_in,
                              void* d_out, int out_size) {
    const float* y_hist = (const float*)d_in[0];
    const float* W_ih   = (const float*)d_in[1];
    const float* W_hh   = (const float*)d_in[2];
    const float* b_ih   = (const float*)d_in[3];
    const float* b_hh   = (const float*)d_in[4];
    const float* W_fc   = (const float*)d_in[5];
    const float* b_fc   = (const float*)d_in[6];
    const float* h0     = (const float*)d_in[7];
    const float* c0     = (const float*)d_in[8];

    cudaFuncSetAttribute(lstm_persist, cudaFuncAttributeMaxDynamicSharedMemorySize, SMEM_SZ);
    lstm_prologue<<<(Bn * Hn) / 256, 256>>>(h0);
    lstm_persist<<<GRID, NTHR, SMEM_SZ>>>(y_hist, W_ih, W_hh, b_ih, b_hh, c0);
    lstm_fc<<<Bn, 32>>>(W_fc, b_fc, (float*)d_out);
}

// round 6
// speedup vs baseline: 1.3262x; 1.3262x over previous
#include <cuda_runtime.h>
#include <cuda_fp16.h>
#include <cstdint>

// B=256, T=512, H=1024 LSTM decoder on sm_103a (PTX target sm_103 baseline:
// NO tcgen05). Persistent kernel, 128 CTAs in 32 clusters of 4.
// gates = h @ W_hh^T via mma.sync m16n8k16 (fp16 in, fp32 acc).
// A (h) chunks delivered by cp.async.bulk + multicast::cluster from a
// pre-swizzled (SW128 atom) global h image. W slice resident in SMEM.

static constexpr int Tn = 512, Bn = 256, Hn = 1024;
static constexpr int GRID = 128, NTHR = 288;   // 8 compute warps + 1 producer warp
static constexpr int NCHUNK = 16;              // K chunks of 64 halfs
static constexpr int CHUNK_B = 16384;          // per-CTA A chunk: 128 rows x 128B
static constexpr int SLICE_B = 4096;           // per-rank multicast slice (32 rows)
static constexpr int IMG_CHUNK = 32768;        // image chunk: 256 rows x 128B
static constexpr int B_STR = 1032;             // W smem stride in halfs (padded)

static constexpr int OFF_FULL = 0;             // 4 mbarriers
static constexpr int OFF_DONE = 32;            // 4 mbarriers
static constexpr int OFF_BIAS = 128;           // 64 f32
static constexpr int OFF_WIN  = 384;           // 64 f32
static constexpr int OFF_A    = 1024;          // 4 x 16KB A buffers
static constexpr int OFF_W    = OFF_A + 4 * CHUNK_B;        // 66560
static constexpr int SMEM_SZ  = OFF_W + 64 * B_STR * 2;     // 198656

__device__ __align__(1024) unsigned char g_himg[2][NCHUNK * IMG_CHUNK];
__device__ float    g_ytr[Tn * Bn];
__device__ unsigned g_bar;

#define SWZ(off) ((off) ^ (((off) >> 3) & 0x70))

// ---------------- helpers ----------------
__device__ __forceinline__ uint32_t smem_u32(const void* p) {
    uint32_t a;
    asm("{ .reg .u64 t; cvta.to.shared.u64 t, %1; cvt.u32.u64 %0, t; }" : "=r"(a) : "l"(p));
    return a;
}
__device__ __forceinline__ uint32_t elect_one() {
    uint32_t p;
    asm volatile("{ .reg .pred p; elect.sync _|p, 0xFFFFFFFF; selp.b32 %0, 1, 0, p; }" : "=r"(p));
    return p;
}
__device__ __forceinline__ unsigned ld_acquire_gpu(const unsigned* p) {
    unsigned v;
    asm volatile("ld.acquire.gpu.global.u32 %0, [%1];" : "=r"(v) : "l"(p) : "memory");
    return v;
}
#define MBARRIER_INIT(addr, cnt) \
    asm volatile("mbarrier.init.shared.b64 [%0], %1;" :: "r"((uint32_t)(addr)), "r"((uint32_t)(cnt)) : "memory")
#define MBARRIER_EXPECT_TX(addr, tx) \
    asm volatile("mbarrier.arrive.expect_tx.shared.b64 _, [%0], %1;" :: "r"((uint32_t)(addr)), "r"((uint32_t)(tx)) : "memory")
#define ARRIVE_CLUSTER(mbar, r) \
    asm volatile("{ .reg .b32 ra; mapa.shared::cluster.u32 ra, %0, %1; " \
                 "mbarrier.arrive.shared::cluster.b64 _, [ra]; }" \
                 :: "r"((uint32_t)(mbar)), "r"((uint32_t)(r)) : "memory")

__device__ __forceinline__ void mbar_wait(uint32_t mbar, uint32_t parity) {
    asm volatile(
        "{\n\t.reg .pred P;\n\t"
        "LAB_%=:\n\t"
        "mbarrier.try_wait.parity.acquire.cta.shared::cta.b64 P, [%0], %1, 0x989680;\n\t"
        "@!P bra LAB_%=;\n\t}"
        :: "r"(mbar), "r"(parity) : "memory");
}
__device__ __forceinline__ void bulk_mcast(uint32_t dst, const void* src, uint32_t bytes,
                                           uint32_t mbar, uint16_t mask) {
    asm volatile(
        "cp.async.bulk.shared::cluster.global.mbarrier::complete_tx::bytes.multicast::cluster"
        " [%0], [%1], %2, [%3], %4;"
        :: "r"(dst), "l"(src), "r"(bytes), "r"(mbar), "h"(mask) : "memory");
}
#define CLUSTER_SYNC() do { \
    asm volatile("barrier.cluster.arrive.aligned;" ::: "memory"); \
    asm volatile("barrier.cluster.wait.aligned;" ::: "memory"); } while (0)

#define LDSM_X4(r0, r1, r2, r3, addr)                                           \
    asm volatile("ldmatrix.sync.aligned.m8n8.x4.shared.b16 {%0,%1,%2,%3},[%4];" \
                 : "=r"(r0), "=r"(r1), "=r"(r2), "=r"(r3) : "r"(addr))

#define MMA16816(d, a, b0v, b1v)                                              \
    asm volatile("mma.sync.aligned.m16n8k16.row.col.f32.f16.f16.f32 "         \
                 "{%0,%1,%2,%3},{%4,%5,%6,%7},{%8,%9},{%0,%1,%2,%3};"         \
                 : "+f"((d)[0]), "+f"((d)[1]), "+f"((d)[2]), "+f"((d)[3])     \
                 : "r"((a)[0]), "r"((a)[1]), "r"((a)[2]), "r"((a)[3]),        \
                   "r"(b0v), "r"(b1v))

__device__ __forceinline__ float tanha(float x) {
    float y; asm("tanh.approx.f32 %0, %1;" : "=f"(y) : "f"(x)); return y;
}
__device__ __forceinline__ float sigt(float x) { return fmaf(tanha(0.5f * x), 0.5f, 0.5f); }

// image byte offset for (row 0..255, half-col k 0..1023)
__device__ __forceinline__ uint32_t img_off(int row, int k) {
    int kc = k >> 6, kl = k & 63;
    uint32_t local = (uint32_t)((row & 7) * 128 + kl * 2);
    return (uint32_t)(kc * IMG_CHUNK + (row >> 3) * 1024) + SWZ(local);
}

// ---------------- prologue: barrier reset, y transpose, h0 -> swizzled image ----------------
__global__ void lstm_prologue(const float* __restrict__ y_hist, const float* __restrict__ h0) {
    int idx = blockIdx.x * 256 + threadIdx.x;          // 512*256 = 131072 = Tn*Bn
    if (idx == 0) g_bar = 0u;
    int t = idx >> 8, b = idx & 255;
    g_ytr[idx] = y_hist[(size_t)b * Tn + t];
    if (idx < 256 * 128) {
        int b2 = idx >> 7, k = (idx & 127) * 8;
        const float* s = h0 + (size_t)b2 * Hn + k;
        __half hv[8];
        #pragma unroll
        for (int j = 0; j < 8; ++j) hv[j] = __float2half(s[j]);
        *(uint4*)(g_himg[0] + img_off(b2, k)) = *(const uint4*)hv;
    }
}

// ---------------- persistent LSTM ----------------
__global__ void __launch_bounds__(NTHR, 1)
lstm_persist(const float* __restrict__ W_ih, const float* __restrict__ W_hh,
             const float* __restrict__ b_ih, const float* __restrict__ b_hh,
             const float* __restrict__ c0) {
    extern __shared__ char smem[];
    const uint32_t sb = smem_u32(smem);
    float* bias_s = (float*)(smem + OFF_BIAS);
    float* win_s  = (float*)(smem + OFF_WIN);

    const int tid = threadIdx.x, lid = tid & 31, wid = tid >> 5;
    const int wm = wid >> 1, wn = wid & 1;              // compute warps: 4M x 2N
    const int bx = blockIdx.x, q = bx >> 2, rank = bx & 3;
    const int mi = q & 1, ci = (q >> 1) * 4 + rank;
    const int m0 = mi * 128, j0 = ci * 16;

    if (tid == 0) {
        #pragma unroll
        for (int b = 0; b < 4; ++b) {
            MBARRIER_INIT(sb + OFF_FULL + b * 8, 1);
            MBARRIER_INIT(sb + OFF_DONE + b * 8, 32);   // 8 warps x 4 CTAs
        }
    }
    if (tid < 64) {
        int gate = tid & 3, jj = tid >> 2;
        int n = gate * Hn + j0 + jj;
        bias_s[tid] = b_ih[n] + b_hh[n];
        win_s[tid]  = W_ih[n];
    }
    // resident W slice: row r = jj*4+gate holds W_hh[gate*1024 + j0+jj][:] fp16
    for (int e = tid; e < 64 * Hn / 8; e += NTHR) {
        int r = e >> 7, kg = (e & 127) << 3;
        int gate = r & 3, jj = r >> 2;
        const float* src = W_hh + (size_t)(gate * Hn + j0 + jj) * Hn + kg;
        float4 f0 = *(const float4*)src;
        float4 f1 = *(const float4*)(src + 4);
        __half hv[8];
        hv[0] = __float2half(f0.x); hv[1] = __float2half(f0.y);
        hv[2] = __float2half(f0.z); hv[3] = __float2half(f0.w);
        hv[4] = __float2half(f1.x); hv[5] = __float2half(f1.y);
        hv[6] = __float2half(f1.z); hv[7] = __float2half(f1.w);
        *(uint4*)(smem + OFF_W + (size_t)(r * B_STR + kg) * 2) = *(const uint4*)hv;
    }
    __syncthreads();
    CLUSTER_SYNC();

    // ldmatrix A offsets (swizzled atoms): row' = wm*32 + mt*16 + (lid&15)
    const int aRowL = lid & 15;
    const int cgB   = (lid >> 4) * 16;      // 0 or 16 bytes (8 halfs)
    int aBase[2], aXor;
    {
        int r0 = wm * 32 + 0 * 16 + aRowL;
        int r1 = wm * 32 + 1 * 16 + aRowL;
        aBase[0] = (r0 >> 3) * 1024 + (r0 & 7) * 128;
        aBase[1] = (r1 >> 3) * 1024 + (r1 & 7) * 128;
        aXor = (r0 & 7) * 16;               // r0&7 == r1&7
    }
    // ldmatrix B offsets (padded linear layout, proven in R4)
    const int bRow  = (lid & 7) + ((lid >> 4) << 3);
    const int bColB = (lid & 8) ? 16 : 0;
    int bOff[2];
    #pragma unroll
    for (int np = 0; np < 2; ++np)
        bOff[np] = OFF_W + ((wn * 32 + np * 16 + bRow) * B_STR) * 2 + bColB;

    // cell state registers
    const int rowL = (lid >> 2) + 8 * (lid & 1);
    const int jjL  = wn * 8 + ((lid & 3) >> 1);
    const int baseRow = m0 + wm * 32 + rowL;
    float cst[8];
    if (wid < 8) {
        #pragma unroll
        for (int mt = 0; mt < 2; ++mt)
            #pragma unroll
            for (int nt = 0; nt < 4; ++nt)
                cst[mt * 4 + nt] = c0[(size_t)(baseRow + mt * 16) * Hn + j0 + jjL + nt * 2];
    }
    const uint32_t src_off = (uint32_t)(mi * 16384 + rank * SLICE_B);
    unsigned bar_tgt = GRID;

    for (int t = 0; t < Tn; ++t) {
        if (wid == 8) {
            if (elect_one()) {
                const unsigned char* img = g_himg[t & 1];
                #pragma unroll 1
                for (int i = 0; i < NCHUNK; ++i) {
                    int b = i & 3;
                    if (t | (i >> 2)) {
                        uint32_t dp = (i < 4) ? 1u : (uint32_t)(((i >> 2) - 1) & 1);
                        mbar_wait(sb + OFF_DONE + b * 8, dp);
                    }
                    MBARRIER_EXPECT_TX(sb + OFF_FULL + b * 8, CHUNK_B);
                    bulk_mcast(sb + OFF_A + b * CHUNK_B + rank * SLICE_B,
                               img + i * IMG_CHUNK + src_off, SLICE_B,
                               sb + OFF_FULL + b * 8, 0xF);
                }
            }
        } else {
            float d[2][4][4] = {};
            #pragma unroll 1
            for (int i = 0; i < NCHUNK; ++i) {
                int b = i & 3;
                mbar_wait(sb + OFF_FULL + b * 8, (uint32_t)((i >> 2) & 1));
                const uint32_t abase = sb + OFF_A + b * CHUNK_B;
                #pragma unroll
                for (int ks = 0; ks < 4; ++ks) {
                    uint32_t a[2][4], bb[2][4];
                    #pragma unroll
                    for (int mt = 0; mt < 2; ++mt) {
                        uint32_t ad = abase + aBase[mt] + ((ks * 32 + cgB) ^ aXor);
                        LDSM_X4(a[mt][0], a[mt][1], a[mt][2], a[mt][3], ad);
                    }
                    #pragma unroll
                    for (int np = 0; np < 2; ++np) {
                        uint32_t bd = sb + bOff[np] + i * 128 + ks * 32;
                        LDSM_X4(bb[np][0], bb[np][1], bb[np][2], bb[np][3], bd);
                    }
                    #pragma unroll
                    for (int mt = 0; mt < 2; ++mt)
                        #pragma unroll
                        for (int nt = 0; nt < 4; ++nt)
                            MMA16816(d[mt][nt], a[mt],
                                     bb[nt >> 1][(nt & 1) * 2], bb[nt >> 1][(nt & 1) * 2 + 1]);
                }
                if (elect_one()) {
                    ARRIVE_CLUSTER(sb + OFF_DONE + b * 8, 0);
                    ARRIVE_CLUSTER(sb + OFF_DONE + b * 8, 1);
                    ARRIVE_CLUSTER(sb + OFF_DONE + b * 8, 2);
                    ARRIVE_CLUSTER(sb + OFF_DONE + b * 8, 3);
                }
            }

            // epilogue: rank-1 x term + bias, gate exchange, LSTM cell, h -> image
            unsigned char* img1 = g_himg[(t + 1) & 1];
            #pragma unroll
            for (int mt = 0; mt < 2; ++mt) {
                float x0 = __ldg(&g_ytr[t * Bn + m0 + wm * 32 + mt * 16 + (lid >> 2)]);
                float x1 = __ldg(&g_ytr[t * Bn + m0 + wm * 32 + mt * 16 + (lid >> 2) + 8]);
                #pragma unroll
                for (int nt = 0; nt < 4; ++nt) {
                    int col0 = wn * 32 + nt * 8 + (lid & 3) * 2;
                    float w0 = win_s[col0], w1 = win_s[col0 + 1];
                    float z0 = bias_s[col0], z1 = bias_s[col0 + 1];
                    float g0 = d[mt][nt][0] + x0 * w0 + z0;
                    float g1 = d[mt][nt][1] + x0 * w1 + z1;
                    float g2 = d[mt][nt][2] + x1 * w0 + z0;
                    float g3 = d[mt][nt][3] + x1 * w1 + z1;
                    float p0 = __shfl_xor_sync(~0u, g0, 1);
                    float p1 = __shfl_xor_sync(~0u, g1, 1);
                    float p2 = __shfl_xor_sync(~0u, g2, 1);
                    float p3 = __shfl_xor_sync(~0u, g3, 1);
                    float gi, gf, gg, go;
                    if ((lid & 1) == 0) { gi = g0; gf = g1; gg = p0; go = p1; }
                    else                { gi = p2; gf = p3; gg = g2; go = g3; }
                    float c_old = cst[mt * 4 + nt];
                    float cn = sigt(gf) * c_old + sigt(gi) * tanha(gg);
                    cst[mt * 4 + nt] = cn;
                    float hn = sigt(go) * tanha(cn);
                    *(__half*)(img1 + img_off(baseRow + mt * 16, j0 + jjL + nt * 2)) =
                        __float2half(hn);
                }
            }
        }

        if (t != Tn - 1) {
            __threadfence();
            __syncthreads();
            if (tid == 0) {
                atomicAdd(&g_bar, 1u);
                while (ld_acquire_gpu(&g_bar) < bar_tgt) { }
            }
            __syncthreads();
            bar_tgt += GRID;
        }
    }
    CLUSTER_SYNC();
}

// ---------------- final FC: out[b] = h_T[b] . W_fc + b_fc (h in image buf 0) ----------------
__global__ void lstm_fc(const float* __restrict__ W_fc, const float* __restrict__ b_fc,
                        float* __restrict__ out) {
    int b = blockIdx.x, l = threadIdx.x;
    float acc = 0.0f;
    #pragma unroll
    for (int it = 0; it < 4; ++it) {
        int kc = it * 4 + (l >> 3), u = l & 7;
        const __half* p = (const __half*)(g_himg[0] + img_off(b, kc * 64 + u * 8));
        const float* w = W_fc + kc * 64 + u * 8;
        #pragma unroll
        for (int j = 0; j < 8; ++j) acc += __half2float(p[j]) * w[j];
    }
    #pragma unroll
    for (int o = 16; o; o >>= 1) acc += __shfl_xor_sync(~0u, acc, o);
    if (l == 0) out[b] = acc + b_fc[0];
}

extern "C" void kernel_launch(void* const* d_in, const int* in_sizes, int n_in,
                              void* d_out, int out_size) {
    const float* y_hist = (const float*)d_in[0];
    const float* W_ih   = (const float*)d_in[1];
    const float* W_hh   = (const float*)d_in[2];
    const float* b_ih   = (const float*)d_in[3];
    const float* b_hh   = (const float*)d_in[4];
    const float* W_fc   = (const float*)d_in[5];
    const float* b_fc   = (const float*)d_in[6];
    const float* h0     = (const float*)d_in[7];
    const float* c0     = (const float*)d_in[8];

    cudaFuncSetAttribute(lstm_persist, cudaFuncAttributeMaxDynamicSharedMemorySize, SMEM_SZ);

    lstm_prologue<<<512, 256>>>(y_hist, h0);

    cudaLaunchConfig_t cfg = {};
    cfg.gridDim = dim3(GRID, 1, 1);
    cfg.blockDim = dim3(NTHR, 1, 1);
    cfg.dynamicSmemBytes = SMEM_SZ;
    cfg.stream = 0;
    cudaLaunchAttribute at[1];
    at[0].id = cudaLaunchAttributeClusterDimension;
    at[0].val.clusterDim.x = 4; at[0].val.clusterDim.y = 1; at[0].val.clusterDim.z = 1;
    cfg.attrs = at;
    cfg.numAttrs = 1;
    cudaLaunchKernelEx(&cfg, lstm_persist, W_ih, W_hh, b_ih, b_hh, c0);

    lstm_fc<<<Bn, 32>>>(W_fc, b_fc, (float*)d_out);
}